// round 11
// baseline (speedup 1.0000x reference)
#include <cuda_runtime.h>
#include <cuda_fp16.h>
#include <cstdint>

#define BATCH 16384
#define DIM   2048
#define NEXP  64
#define MT    128                // rows per CTA
#define BK    64                 // k elems per chunk (fp16 rows = 128B -> SW128)
#define NCHUNK (DIM / BK)        // 32
#define NTH   256
#define LG_STR 66
#define TIE_TH 1e-4f

#define A_PLANE 16384            // 128*64*2 bytes per limb
#define B_PLANE 8192             // 64*64*2 bytes per limb
#define STAGE   (2 * A_PLANE + 2 * B_PLANE)   // 49152
#define SMEM_DYN (2 * STAGE)                   // 98304

#define SWZ(o) ((uint32_t)(o) ^ ((((uint32_t)(o)) >> 3) & 0x70))

// W fp16 limbs, precomputed once (512KB total, L2-resident)
__device__ __half g_Wh[NEXP * DIM];
__device__ __half g_Wm[NEXP * DIM];
// near-tie flags, rewritten for every row each launch (no reset needed)
__device__ unsigned char g_flag[BATCH];

__device__ __forceinline__ uint32_t smem_u32(const void* p) {
    uint32_t a;
    asm("{ .reg .u64 t; cvta.to.shared.u64 t, %1; cvt.u32.u64 %0, t; }"
        : "=r"(a) : "l"(p));
    return a;
}

__device__ __forceinline__ void split2h(float a, float b,
                                        uint32_t& h, uint32_t& m) {
    __half2 H, M;
    H.x = __float2half_rn(a);  H.y = __float2half_rn(b);
    float ra = a - __half2float(H.x), rb = b - __half2float(H.y);
    M.x = __float2half_rn(ra); M.y = __float2half_rn(rb);
    h = *reinterpret_cast<uint32_t*>(&H);
    m = *reinterpret_cast<uint32_t*>(&M);
}

#define LDSM4(r0, r1, r2, r3, a)                                              \
    asm volatile("ldmatrix.sync.aligned.m8n8.x4.shared.b16 {%0,%1,%2,%3},[%4];" \
                 : "=r"(r0), "=r"(r1), "=r"(r2), "=r"(r3) : "r"(a))
#define MMA16816(c, a0, a1, a2, a3, b0, b1)                                   \
    asm volatile("mma.sync.aligned.m16n8k16.row.col.f32.f16.f16.f32 "         \
                 "{%0,%1,%2,%3},{%4,%5,%6,%7},{%8,%9},{%0,%1,%2,%3};"         \
                 : "+f"((c)[0]), "+f"((c)[1]), "+f"((c)[2]), "+f"((c)[3])     \
                 : "r"(a0), "r"(a1), "r"(a2), "r"(a3), "r"(b0), "r"(b1))
#define CP_ASYNC16(dst, src)                                                  \
    asm volatile("cp.async.cg.shared.global [%0], [%1], 16;"                  \
                 :: "r"(dst), "l"(src) : "memory")
#define CP_COMMIT() asm volatile("cp.async.commit_group;" ::: "memory")
#define CP_WAIT0()  asm volatile("cp.async.wait_group 0;" ::: "memory")

// ---------------- W limb prep (once) ----------------
__global__ __launch_bounds__(256)
void prep_w_kernel(const float* __restrict__ W) {
    int i4 = blockIdx.x * 256 + threadIdx.x;       // 32768 float4 total
    float4 v = reinterpret_cast<const float4*>(W)[i4];
    uint2 hu, mu;
    split2h(v.x, v.y, hu.x, mu.x);
    split2h(v.z, v.w, hu.y, mu.y);
    reinterpret_cast<uint2*>(g_Wh)[i4] = hu;
    reinterpret_cast<uint2*>(g_Wm)[i4] = mu;
}

// ---------------- fused GEMM + top2 + softmax ----------------
__global__ __launch_bounds__(NTH)
void gate_kernel(const float* __restrict__ x,
                 const float* __restrict__ bias,
                 float* __restrict__ out) {
    extern __shared__ char dyn[];
    __shared__ float s_bias[NEXP];

    const int tid  = threadIdx.x;
    const int wid  = tid >> 5;
    const int lane = tid & 31;
    const int row0 = blockIdx.x * MT;
    const int wm   = wid >> 1;           // 0..3 : 32-row block
    const int wn   = wid & 1;            // 0..1 : 32-expert block
    const int grp  = lane >> 3;

    const uint32_t dynb = smem_u32(dyn);
    if (tid < NEXP) s_bias[tid] = bias[tid];

    float acc[2][4][4];                  // [mtile][ntile][frag]
    #pragma unroll
    for (int mt = 0; mt < 2; mt++)
        #pragma unroll
        for (int nt = 0; nt < 4; nt++)
            #pragma unroll
            for (int q = 0; q < 4; q++) acc[mt][nt][q] = 0.0f;

    // ---- register prefetch of A (fp32) ----
    float4 xa[8];
    const float* xbase = x + (size_t)row0 * DIM;

#define LOADA(t)                                                               \
    {                                                                          \
        _Pragma("unroll")                                                      \
        for (int j = 0; j < 8; j++) {                                          \
            int i = j * NTH + tid;                                             \
            int r = i >> 4, k4 = i & 15;                                       \
            xa[j] = *(const float4*)(xbase + (size_t)r * DIM + (t) * BK + k4 * 4); \
        }                                                                      \
    }

#define CPB(t, st)                                                             \
    {                                                                          \
        _Pragma("unroll")                                                      \
        for (int j = 0; j < 4; j++) {                                          \
            int s = j * NTH + tid;                                             \
            int limb = s >> 9, e = (s >> 3) & 63, u = s & 7;                   \
            const __half* src = (limb ? g_Wm : g_Wh) + (size_t)e * DIM + (t) * BK + u * 8; \
            uint32_t dst = dynb + (st) * STAGE + 2 * A_PLANE + limb * B_PLANE  \
                         + SWZ(e * 128 + u * 16);                              \
            CP_ASYNC16(dst, src);                                              \
        }                                                                      \
        CP_COMMIT();                                                           \
    }

#define STSA(st)                                                               \
    {                                                                          \
        _Pragma("unroll")                                                      \
        for (int j = 0; j < 8; j++) {                                          \
            int i = j * NTH + tid;                                             \
            int r = i >> 4, k4 = i & 15;                                       \
            uint2 hu, mu;                                                      \
            split2h(xa[j].x, xa[j].y, hu.x, mu.x);                             \
            split2h(xa[j].z, xa[j].w, hu.y, mu.y);                             \
            uint32_t off = SWZ(r * 128 + k4 * 8);                              \
            *(uint2*)(dyn + (st) * STAGE + off)           = hu;                \
            *(uint2*)(dyn + (st) * STAGE + A_PLANE + off) = mu;                \
        }                                                                      \
    }

    LOADA(0);
    CPB(0, 0);
    CP_WAIT0();
    STSA(0);
    __syncthreads();

    for (int t = 0; t < NCHUNK; t++) {
        const int st = t & 1;
        const uint32_t sb = dynb + st * STAGE;
        if (t + 1 < NCHUNK) {
            LOADA(t + 1);
            CPB(t + 1, 1 - st);
        }
        // ---- compute chunk: 4 k16 steps ----
        #pragma unroll
        for (int ks = 0; ks < 4; ks++) {
            const int k0 = ks * 16;
            // A frags: [mt][limb]
            uint32_t ah[2][4], am[2][4];
            #pragma unroll
            for (int mt = 0; mt < 2; mt++) {
                int r  = wm * 32 + mt * 16 + (lane & 7) + ((grp & 1) << 3);
                int kb = k0 + ((grp >> 1) << 3);
                uint32_t off = SWZ(r * 128 + kb * 2);
                LDSM4(ah[mt][0], ah[mt][1], ah[mt][2], ah[mt][3], sb + off);
                LDSM4(am[mt][0], am[mt][1], am[mt][2], am[mt][3], sb + A_PLANE + off);
            }
            #pragma unroll
            for (int ng = 0; ng < 2; ng++) {
                // non-trans: address lanes supply expert rows; x4 matrices =
                // (n0-7,k0-7),(n0-7,k8-15),(n8-15,k0-7),(n8-15,k8-15)
                int e  = wn * 32 + ng * 16 + (lane & 7) + ((grp >> 1) << 3);
                int kb = k0 + ((grp & 1) << 3);
                uint32_t off = SWZ(e * 128 + kb * 2);
                uint32_t bh[4], bm[4];
                LDSM4(bh[0], bh[1], bh[2], bh[3], sb + 2 * A_PLANE + off);
                LDSM4(bm[0], bm[1], bm[2], bm[3], sb + 2 * A_PLANE + B_PLANE + off);
                #pragma unroll
                for (int sub = 0; sub < 2; sub++) {
                    int nt = ng * 2 + sub;
                    #pragma unroll
                    for (int mt = 0; mt < 2; mt++) {
                        MMA16816(acc[mt][nt], ah[mt][0], ah[mt][1], ah[mt][2], ah[mt][3],
                                 bh[2 * sub], bh[2 * sub + 1]);
                        MMA16816(acc[mt][nt], ah[mt][0], ah[mt][1], ah[mt][2], ah[mt][3],
                                 bm[2 * sub], bm[2 * sub + 1]);
                        MMA16816(acc[mt][nt], am[mt][0], am[mt][1], am[mt][2], am[mt][3],
                                 bh[2 * sub], bh[2 * sub + 1]);
                    }
                }
            }
        }
        if (t + 1 < NCHUNK) {
            CP_WAIT0();
            STSA(1 - st);
            __syncthreads();
        }
    }

    __syncthreads();   // all compute done; smem becomes logits buffer

    // ---- scatter accumulators into logits smem ----
    float* logits = (float*)dyn;
    #pragma unroll
    for (int mt = 0; mt < 2; mt++) {
        #pragma unroll
        for (int nt = 0; nt < 4; nt++) {
            int r0r = wm * 32 + mt * 16 + (lane >> 2);
            int c0  = wn * 32 + nt * 8 + (lane & 3) * 2;
            *(float2*)&logits[(r0r    ) * LG_STR + c0] = make_float2(acc[mt][nt][0], acc[mt][nt][1]);
            *(float2*)&logits[(r0r + 8) * LG_STR + c0] = make_float2(acc[mt][nt][2], acc[mt][nt][3]);
        }
    }
    __syncthreads();

    // ---- per-row top-3 + softmax + tie flag (threads 0..127) ----
    if (tid < MT) {
        const int r = tid;
        float l1 = -1e30f, l2 = -1e30f, l3 = -1e30f;
        int   i1 = 0,      i2 = 0;
        #pragma unroll 8
        for (int e = 0; e < NEXP; e++) {
            float v = logits[r * LG_STR + e] + s_bias[e];
            if (v > l1)      { l3 = l2; l2 = l1; i2 = i1; l1 = v; i1 = e; }
            else if (v > l2) { l3 = l2; l2 = v;  i2 = e; }
            else if (v > l3) { l3 = v; }
        }
        float e2    = expf(l2 - l1);
        float denom = 1.0f + e2;
        const int gr = row0 + r;
        out[2 * gr]                 = 1.0f / denom;
        out[2 * gr + 1]             = e2 / denom;
        out[2 * BATCH + 2 * gr]     = (float)i1;
        out[2 * BATCH + 2 * gr + 1] = (float)i2;
        g_flag[gr] = ((l1 - l2 < TIE_TH) || (l2 - l3 < TIE_TH)) ? 1 : 0;
    }
}

// ---------------- exact fp32 fixup for near-tie rows ----------------
__global__ __launch_bounds__(256)
void fixup_kernel(const float* __restrict__ x,
                  const float* __restrict__ W,
                  const float* __restrict__ bias,
                  float* __restrict__ out) {
    const int lane = threadIdx.x & 31;
    const int wg   = (blockIdx.x * 256 + threadIdx.x) >> 5;   // 0..511
    for (int rr = 0; rr < 32; rr++) {
        const int row = wg * 32 + rr;
        if (!g_flag[row]) continue;                 // uniform per warp
        const float4* x4 = (const float4*)(x + (size_t)row * DIM);
        float4 xr[16];
        #pragma unroll
        for (int j = 0; j < 16; j++) xr[j] = x4[j * 32 + lane];
        float l1 = -1e30f, l2 = -1e30f;
        int   i1 = 0,      i2 = 0;
        for (int e = 0; e < NEXP; e++) {
            const float4* w4 = (const float4*)(W + (size_t)e * DIM);
            float s = 0.0f;
            #pragma unroll
            for (int j = 0; j < 16; j++) {
                float4 w = w4[j * 32 + lane];
                s += xr[j].x * w.x + xr[j].y * w.y
                   + xr[j].z * w.z + xr[j].w * w.w;
            }
            #pragma unroll
            for (int o = 16; o; o >>= 1)
                s += __shfl_xor_sync(0xFFFFFFFFu, s, o);
            s += bias[e];
            if (s > l1)      { l2 = l1; i2 = i1; l1 = s; i1 = e; }
            else if (s > l2) { l2 = s;  i2 = e; }
        }
        if (lane == 0) {
            float e2    = expf(l2 - l1);
            float denom = 1.0f + e2;
            out[2 * row]                 = 1.0f / denom;
            out[2 * row + 1]             = e2 / denom;
            out[2 * BATCH + 2 * row]     = (float)i1;
            out[2 * BATCH + 2 * row + 1] = (float)i2;
        }
    }
}

extern "C" void kernel_launch(void* const* d_in, const int* in_sizes, int n_in,
                              void* d_out, int out_size) {
    const float* x = (const float*)d_in[0];
    const float* W = (const float*)d_in[1];
    const float* b = (const float*)d_in[2];
    float* out = (float*)d_out;
    (void)in_sizes; (void)n_in; (void)out_size;
    cudaFuncSetAttribute(gate_kernel,
                         cudaFuncAttributeMaxDynamicSharedMemorySize, SMEM_DYN);
    prep_w_kernel<<<128, 256>>>(W);
    gate_kernel<<<BATCH / MT, NTH, SMEM_DYN>>>(x, b, out);
    fixup_kernel<<<BATCH / (32 * 8), 256>>>(x, W, b, out);
}

// round 12
// speedup vs baseline: 1.2515x; 1.2515x over previous
#include <cuda_runtime.h>
#include <cstdint>

#define BATCH 16384
#define DIM   2048
#define NEXP  64
#define BM    64
#define BK    32
#define KSPLIT 2
#define KPER  (DIM / KSPLIT)     // 1024
#define NTILES (KPER / BK)       // 32
#define NTH   256
#define XS_STR 260               // floats per kf2 row: 1040B, 16B-aligned, bank-staggered
#define LG_STR 68

#define XS_BYTES (16 * XS_STR * 4)            // 16640
#define WS_BYTES (NEXP * BK * 4)              // 8192
#define STAGE_BYTES (XS_BYTES + WS_BYTES)     // 24832
#define SMEM_DYN (2 * STAGE_BYTES)            // 49664

__device__ float g_part[KSPLIT][BATCH][NEXP];   // 8MB split-K partials
__device__ int   g_cnt[BATCH / BM];             // zero-init; reset after use

__device__ __forceinline__ void ffma2(unsigned long long& acc,
                                      unsigned long long a,
                                      unsigned long long w) {
    asm("fma.rn.f32x2 %0, %1, %2, %0;" : "+l"(acc) : "l"(a), "l"(w));
}
__device__ __forceinline__ unsigned long long dup2(float v) {
    float2 d = make_float2(v, v);
    return *(unsigned long long*)&d;
}
__device__ __forceinline__ unsigned long long pack2(float a, float b) {
    float2 d = make_float2(a, b);
    return *(unsigned long long*)&d;
}
__device__ __forceinline__ uint32_t smem_u32(const void* p) {
    uint32_t a;
    asm("{ .reg .u64 t; cvta.to.shared.u64 t, %1; cvt.u32.u64 %0, t; }"
        : "=r"(a) : "l"(p));
    return a;
}
#define CP_ASYNC16(dst, src)                                                  \
    asm volatile("cp.async.cg.shared.global [%0], [%1], 16;"                  \
                 :: "r"(dst), "l"(src) : "memory")
#define CP_COMMIT() asm volatile("cp.async.commit_group;" ::: "memory")
#define CP_WAIT0()  asm volatile("cp.async.wait_group 0;" ::: "memory")

__global__ __launch_bounds__(NTH)
void gate_kernel(const float* __restrict__ x,
                 const float* __restrict__ W,
                 const float* __restrict__ bias,
                 float* __restrict__ out) {
    extern __shared__ char dyn[];
    __shared__ int s_last;

    const int tid  = threadIdx.x;
    const int wid  = tid >> 5;
    const int lane = tid & 31;
    const int rb   = blockIdx.x;          // row block 0..255
    const int ks   = blockIdx.y;          // k-split 0..1
    const int row0 = rb * BM;
    const int ksbase = ks * KPER;

    const int wr = wid & 3;               // 16-row block
    const int we = wid >> 2;              // 32-expert block
    const int el = lane & 7;              // expert slot within group of 8
    const int pg = lane >> 3;             // pair-group 0..3
    const int P0 = wr * 8 + pg * 2;       // first of 2 row-pairs
    int ej[4];
    #pragma unroll
    for (int j = 0; j < 4; j++) ej[j] = we * 32 + el + 8 * j;

    const uint32_t dynb = smem_u32(dyn);

    // acc[p][j]: rows (2*(P0+p), 2*(P0+p)+1), expert ej[j]
    unsigned long long acc[2][4];
    #pragma unroll
    for (int p = 0; p < 2; p++)
        #pragma unroll
        for (int j = 0; j < 4; j++) acc[p][j] = 0ull;

    float2 xv[2][2];                       // register prefetch of x tile

#define LOADX(t)                                                               \
    {                                                                          \
        _Pragma("unroll")                                                      \
        for (int s = 0; s < 2; s++) {                                          \
            int c = s * NTH + tid;                                             \
            int kf2c = c & 15, r2c = c >> 4;                                   \
            const float* p = x + (size_t)(row0 + 2 * r2c) * DIM                \
                           + ksbase + (t) * BK + 2 * kf2c;                     \
            xv[s][0] = *(const float2*)p;                                      \
            xv[s][1] = *(const float2*)(p + DIM);                              \
        }                                                                      \
    }

#define STSX(st)                                                               \
    {                                                                          \
        _Pragma("unroll")                                                      \
        for (int s = 0; s < 2; s++) {                                          \
            int c = s * NTH + tid;                                             \
            int kf2c = c & 15, r2c = c >> 4;                                   \
            float4 v = make_float4(xv[s][0].x, xv[s][1].x,                     \
                                   xv[s][0].y, xv[s][1].y);                    \
            *(float4*)(dyn + (st) * STAGE_BYTES                                \
                       + (kf2c * XS_STR + r2c * 4) * 4) = v;                   \
        }                                                                      \
    }

#define CPW(t, st)                                                             \
    {                                                                          \
        _Pragma("unroll")                                                      \
        for (int s = 0; s < 2; s++) {                                          \
            int c = s * NTH + tid;                                             \
            int kf4c = c & 7, ec = (c >> 3) & 63;                              \
            const float* src = W + (size_t)ec * DIM + ksbase + (t) * BK        \
                             + kf4c * 4;                                       \
            uint32_t dst = dynb + (st) * STAGE_BYTES + XS_BYTES                \
                         + (ec * 32 + ((kf4c ^ (ec & 7)) << 2)) * 4;           \
            CP_ASYNC16(dst, src);                                              \
        }                                                                      \
        CP_COMMIT();                                                           \
    }

    LOADX(0);
    CPW(0, 0);
    STSX(0);
    CP_WAIT0();
    __syncthreads();

    for (int t = 0; t < NTILES; t++) {
        const int st = t & 1;
        const float* xsp = (const float*)(dyn + st * STAGE_BYTES);
        const float* wsp = (const float*)(dyn + st * STAGE_BYTES + XS_BYTES);
        if (t + 1 < NTILES) {
            LOADX(t + 1);
            CPW(t + 1, 1 - st);
        }
        #pragma unroll
        for (int kf4 = 0; kf4 < 8; kf4++) {
            float4 w4[4];
            #pragma unroll
            for (int j = 0; j < 4; j++)
                w4[j] = *(const float4*)&wsp[ej[j] * 32 + ((kf4 ^ el) << 2)];
            #pragma unroll
            for (int h = 0; h < 2; h++) {
                int kf2 = kf4 * 2 + h;
                float4 a0 = *(const float4*)&xsp[kf2 * XS_STR + (P0 << 2)];
                float4 a1 = *(const float4*)&xsp[kf2 * XS_STR + ((P0 + 1) << 2)];
                #pragma unroll
                for (int j = 0; j < 4; j++) {
                    float wk  = h ? w4[j].z : w4[j].x;
                    float wk1 = h ? w4[j].w : w4[j].y;
                    unsigned long long dk  = dup2(wk);
                    unsigned long long dk1 = dup2(wk1);
                    ffma2(acc[0][j], pack2(a0.x, a0.y), dk);
                    ffma2(acc[0][j], pack2(a0.z, a0.w), dk1);
                    ffma2(acc[1][j], pack2(a1.x, a1.y), dk);
                    ffma2(acc[1][j], pack2(a1.z, a1.w), dk1);
                }
            }
        }
        if (t + 1 < NTILES) {
            CP_WAIT0();
            STSX(1 - st);
        }
        __syncthreads();
    }

    // ---- stage partial logits into smem (reuse stage area) ----
    float* logits = (float*)dyn;
    #pragma unroll
    for (int p = 0; p < 2; p++) {
        int r = 2 * (P0 + p);
        #pragma unroll
        for (int j = 0; j < 4; j++) {
            float2 v = *(float2*)&acc[p][j];
            logits[(r    ) * LG_STR + ej[j]] = v.x;
            logits[(r + 1) * LG_STR + ej[j]] = v.y;
        }
    }
    __syncthreads();

    // ---- coalesced partial store: thread covers 64B of one row ----
    {
        int r = tid >> 2, q = tid & 3;
        float* dst = &g_part[ks][row0 + r][q * 16];
        #pragma unroll
        for (int i = 0; i < 4; i++)
            *(float4*)(dst + 4 * i) = *(const float4*)&logits[r * LG_STR + q * 16 + 4 * i];
    }

    // ---- last CTA of this row block reduces ----
    if (tid == 0) {
        __threadfence();
        s_last = (atomicAdd(&g_cnt[rb], 1) == KSPLIT - 1);
    }
    __syncthreads();
    if (!s_last) return;
    __threadfence();

    if (tid < BM) {
        const int gr = row0 + tid;
        float l1 = -1e30f, l2 = -1e30f;
        int   i1 = 0,      i2 = 0;
        #pragma unroll
        for (int e4 = 0; e4 < NEXP / 4; e4++) {
            float4 p0 = *(const float4*)&g_part[0][gr][4 * e4];
            float4 p1 = *(const float4*)&g_part[1][gr][4 * e4];
            float4 b4 = *(const float4*)&bias[4 * e4];
            float v[4] = {p0.x + p1.x + b4.x, p0.y + p1.y + b4.y,
                          p0.z + p1.z + b4.z, p0.w + p1.w + b4.w};
            #pragma unroll
            for (int c = 0; c < 4; c++) {
                int e = 4 * e4 + c;
                if (v[c] > l1)      { l2 = l1; i2 = i1; l1 = v[c]; i1 = e; }
                else if (v[c] > l2) { l2 = v[c]; i2 = e; }
            }
        }
        float e2    = expf(l2 - l1);
        float denom = 1.0f + e2;
        out[2 * gr]                 = 1.0f / denom;
        out[2 * gr + 1]             = e2 / denom;
        out[2 * BATCH + 2 * gr]     = (float)i1;
        out[2 * BATCH + 2 * gr + 1] = (float)i2;
    }
    if (tid == 0) g_cnt[rb] = 0;    // re-arm for graph replay
}

extern "C" void kernel_launch(void* const* d_in, const int* in_sizes, int n_in,
                              void* d_out, int out_size) {
    const float* x = (const float*)d_in[0];
    const float* W = (const float*)d_in[1];
    const float* b = (const float*)d_in[2];
    float* out = (float*)d_out;
    (void)in_sizes; (void)n_in; (void)out_size;
    cudaFuncSetAttribute(gate_kernel,
                         cudaFuncAttributeMaxDynamicSharedMemorySize, SMEM_DYN);
    gate_kernel<<<dim3(BATCH / BM, KSPLIT), NTH, SMEM_DYN>>>(x, W, b, out);
}

// round 13
// speedup vs baseline: 1.3715x; 1.0959x over previous
#include <cuda_runtime.h>
#include <cstdint>

#define BATCH 16384
#define DIM   2048
#define NEXP  64
#define BM    128
#define BK    32
#define KSPLIT 2
#define KPER  (DIM / KSPLIT)     // 1024
#define NTILES (KPER / BK)       // 32
#define NTH   256
#define LG_STR 68

#define X_BYTES (BM * BK * 4)                 // 16384
#define W_BYTES (NEXP * BK * 4)               // 8192
#define STAGE_BYTES (X_BYTES + W_BYTES)       // 24576
#define SMEM_DYN (2 * STAGE_BYTES)            // 49152

__device__ float g_part[KSPLIT][BATCH][NEXP];   // 8MB split-K partials
__device__ int   g_cnt[BATCH / BM];             // zero-init; re-armed after use

__device__ __forceinline__ void ffma2(unsigned long long& acc,
                                      unsigned long long a,
                                      unsigned long long w) {
    asm("fma.rn.f32x2 %0, %1, %2, %0;" : "+l"(acc) : "l"(a), "l"(w));
}
__device__ __forceinline__ uint32_t smem_u32(const void* p) {
    uint32_t a;
    asm("{ .reg .u64 t; cvta.to.shared.u64 t, %1; cvt.u32.u64 %0, t; }"
        : "=r"(a) : "l"(p));
    return a;
}
#define CP_ASYNC16(dst, src)                                                  \
    asm volatile("cp.async.cg.shared.global [%0], [%1], 16;"                  \
                 :: "r"(dst), "l"(src) : "memory")
#define CP_COMMIT() asm volatile("cp.async.commit_group;" ::: "memory")
#define CP_WAIT0()  asm volatile("cp.async.wait_group 0;" ::: "memory")

__global__ __launch_bounds__(NTH, 2)
void gate_kernel(const float* __restrict__ x,
                 const float* __restrict__ W,
                 const float* __restrict__ bias,
                 float* __restrict__ out) {
    extern __shared__ char dyn[];
    __shared__ int s_last;

    const int tid  = threadIdx.x;
    const int wid  = tid >> 5;            // 8 warps, each 16 rows x 64 experts
    const int lane = tid & 31;
    const int pg   = lane >> 3;           // 0..3 row slot
    const int el   = lane & 7;            // 0..7 expert slot
    const int rb   = blockIdx.x;          // row block 0..127
    const int ks   = blockIdx.y;          // k-split 0..1
    const int row0 = rb * BM;
    const int ksbase = ks * KPER;

    const uint32_t dynb = smem_u32(dyn);

    // acc[i][j]: row wid*16 + 4*i + pg, expert el + 8*j.
    // acc.x = sum over even k, acc.y = sum over odd k.
    unsigned long long acc[4][8];
    #pragma unroll
    for (int i = 0; i < 4; i++)
        #pragma unroll
        for (int j = 0; j < 8; j++) acc[i][j] = 0ull;

#define CPX(t, st)                                                             \
    {                                                                          \
        _Pragma("unroll")                                                      \
        for (int s = 0; s < 4; s++) {                                          \
            int c = s * NTH + tid;           /* 0..1023 */                     \
            int r = c >> 3, k4 = c & 7;                                        \
            const float* src = x + (size_t)(row0 + r) * DIM + ksbase           \
                             + (t) * BK + k4 * 4;                              \
            uint32_t dst = dynb + (st) * STAGE_BYTES + r * 128                 \
                         + ((k4 ^ (r & 7)) << 4);                              \
            CP_ASYNC16(dst, src);                                              \
        }                                                                      \
    }
#define CPW(t, st)                                                             \
    {                                                                          \
        _Pragma("unroll")                                                      \
        for (int s = 0; s < 2; s++) {                                          \
            int c = s * NTH + tid;           /* 0..511 */                      \
            int e = c >> 3, k4 = c & 7;                                        \
            const float* src = W + (size_t)e * DIM + ksbase                    \
                             + (t) * BK + k4 * 4;                              \
            uint32_t dst = dynb + (st) * STAGE_BYTES + X_BYTES + e * 128       \
                         + ((k4 ^ (e & 7)) << 4);                              \
            CP_ASYNC16(dst, src);                                              \
        }                                                                      \
    }

    CPX(0, 0); CPW(0, 0); CP_COMMIT();
    CP_WAIT0();
    __syncthreads();

    for (int t = 0; t < NTILES; t++) {
        const int st = t & 1;
        const char* sb = dyn + st * STAGE_BYTES;
        if (t + 1 < NTILES) { CPX(t + 1, 1 - st); CPW(t + 1, 1 - st); CP_COMMIT(); }

        #pragma unroll
        for (int kf4 = 0; kf4 < 8; kf4++) {
            // a: 4 rows, 16B each (k..k+3), conflict-free + 8-lane broadcast
            ulonglong2 a4[4];
            #pragma unroll
            for (int i = 0; i < 4; i++) {
                int r = wid * 16 + 4 * i + pg;
                a4[i] = *(const ulonglong2*)(sb + r * 128 + ((kf4 ^ (r & 7)) << 4));
            }
            #pragma unroll
            for (int jb = 0; jb < 2; jb++) {
                ulonglong2 w4[4];
                #pragma unroll
                for (int jj = 0; jj < 4; jj++) {
                    int e = el + 8 * (jb * 4 + jj);   // e & 7 == el
                    w4[jj] = *(const ulonglong2*)(sb + X_BYTES + e * 128
                                                  + ((kf4 ^ el) << 4));
                }
                #pragma unroll
                for (int jj = 0; jj < 4; jj++) {
                    int j = jb * 4 + jj;
                    #pragma unroll
                    for (int i = 0; i < 4; i++) {
                        ffma2(acc[i][j], a4[i].x, w4[jj].x);   // k, k+1
                        ffma2(acc[i][j], a4[i].y, w4[jj].y);   // k+2, k+3
                    }
                }
            }
        }
        if (t + 1 < NTILES) CP_WAIT0();
        __syncthreads();
    }

    // ---- stage partial logits into smem ----
    float* logits = (float*)dyn;
    #pragma unroll
    for (int i = 0; i < 4; i++) {
        int r = wid * 16 + 4 * i + pg;
        #pragma unroll
        for (int j = 0; j < 8; j++) {
            float2 v = *(float2*)&acc[i][j];
            logits[r * LG_STR + el + 8 * j] = v.x + v.y;
        }
    }
    __syncthreads();

    // ---- coalesced partial store: thread covers 128B of one row ----
    {
        int r = tid >> 1, h = tid & 1;
        float* dst = &g_part[ks][row0 + r][h * 32];
        #pragma unroll
        for (int i = 0; i < 8; i++)
            *(float4*)(dst + 4 * i) =
                *(const float4*)&logits[r * LG_STR + h * 32 + 4 * i];
    }

    // ---- last CTA of this row block reduces ----
    if (tid == 0) {
        __threadfence();
        s_last = (atomicAdd(&g_cnt[rb], 1) == KSPLIT - 1);
    }
    __syncthreads();
    if (!s_last) return;
    __threadfence();

    if (tid < BM) {
        const int gr = row0 + tid;
        float l1 = -1e30f, l2 = -1e30f;
        int   i1 = 0,      i2 = 0;
        #pragma unroll
        for (int e4 = 0; e4 < NEXP / 4; e4++) {
            float4 p0 = *(const float4*)&g_part[0][gr][4 * e4];
            float4 p1 = *(const float4*)&g_part[1][gr][4 * e4];
            float4 b4 = *(const float4*)&bias[4 * e4];
            float v[4] = {p0.x + p1.x + b4.x, p0.y + p1.y + b4.y,
                          p0.z + p1.z + b4.z, p0.w + p1.w + b4.w};
            #pragma unroll
            for (int c = 0; c < 4; c++) {
                int e = 4 * e4 + c;
                if (v[c] > l1)      { l2 = l1; i2 = i1; l1 = v[c]; i1 = e; }
                else if (v[c] > l2) { l2 = v[c]; i2 = e; }
            }
        }
        float e2    = expf(l2 - l1);
        float denom = 1.0f + e2;
        out[2 * gr]                 = 1.0f / denom;
        out[2 * gr + 1]             = e2 / denom;
        out[2 * BATCH + 2 * gr]     = (float)i1;
        out[2 * BATCH + 2 * gr + 1] = (float)i2;
    }
    if (tid == 0) g_cnt[rb] = 0;    // re-arm for graph replay
}

extern "C" void kernel_launch(void* const* d_in, const int* in_sizes, int n_in,
                              void* d_out, int out_size) {
    const float* x = (const float*)d_in[0];
    const float* W = (const float*)d_in[1];
    const float* b = (const float*)d_in[2];
    float* out = (float*)d_out;
    (void)in_sizes; (void)n_in; (void)out_size;
    cudaFuncSetAttribute(gate_kernel,
                         cudaFuncAttributeMaxDynamicSharedMemorySize, SMEM_DYN);
    gate_kernel<<<dim3(BATCH / BM, KSPLIT), NTH, SMEM_DYN>>>(x, W, b, out);
}